// round 12
// baseline (speedup 1.0000x reference)
#include <cuda_runtime.h>
#include <math.h>
#include <stdint.h>

#define B_ 8
#define H_ 256
#define P_ 1024
#define K_ 32
#define E_ 4
#define BN_ 64
#define W1COLS 516
#define CAUG 260          // 256 nbr + 4 edge rows (augmented contraction)
#define WSTR 68           // W row stride (floats), 272B: 16B-aligned rows
#define XSTR 132          // x row stride (floats), 528B: 16B-aligned rows
#define PT 4              // p's per CTA tile
#define HALF_ROWS 130

#define MAIN_SMEM_FLOATS (CAUG*XSTR + CAUG*WSTR + PT*BN_ + 8*PT*32 + PT*32 + PT*32 + 64)
#define MAIN_SMEM_BYTES  (MAIN_SMEM_FLOATS * 4)

#define BIAS_SMEM_FLOATS (256*WSTR + 256*33 + 64)
#define BIAS_SMEM_BYTES  (BIAS_SMEM_FLOATS * 4)

// scratch: bias[b][p][o] = b1[o] + sum_c current[b,c,p] * w1c[o,c]
__device__ float g_bias[B_ * P_ * BN_];

// ---- packed fp32x2 helpers ----
static __device__ __forceinline__ unsigned long long pack2(float x) {
    unsigned long long r;
    asm("mov.b64 %0, {%1, %1};" : "=l"(r) : "f"(x));
    return r;
}
static __device__ __forceinline__ unsigned long long fma2(unsigned long long a,
                                                          unsigned long long b,
                                                          unsigned long long c) {
    unsigned long long d;
    asm("fma.rn.f32x2 %0, %1, %2, %3;" : "=l"(d) : "l"(a), "l"(b), "l"(c));
    return d;
}
static __device__ __forceinline__ float2 unpack2(unsigned long long v) {
    float2 f;
    asm("mov.b64 {%0, %1}, %2;" : "=f"(f.x), "=f"(f.y) : "l"(v));
    return f;
}
static __device__ __forceinline__ void cp16(uint32_t dst, const void* src) {
    asm volatile("cp.async.cg.shared.global [%0], [%1], 16;" :: "r"(dst), "l"(src));
}

// ===================== kernel A: bias precompute =====================
__global__ void __launch_bounds__(256, 2)
bias_kernel(const float* __restrict__ current,
            const float* __restrict__ w1,
            const float* __restrict__ b1) {
    extern __shared__ float sm[];
    float* wc  = sm;                    // [256][WSTR]
    float* cur = wc + 256 * WSTR;       // [256][33]
    float* b1s = cur + 256 * 33;        // [64]

    const int b  = blockIdx.x >> 5;
    const int p0 = (blockIdx.x & 31) << 5;
    const int t  = threadIdx.x;

    for (int idx = t; idx < 256 * 64; idx += 256) {
        int o = idx >> 8, c = idx & 255;
        wc[c * WSTR + o] = w1[o * W1COLS + c];
    }
    for (int idx = t; idx < 256 * 32; idx += 256) {
        int c = idx >> 5, pl = idx & 31;
        cur[c * 33 + pl] = current[(b * H_ + c) * P_ + p0 + pl];
    }
    if (t < 64) b1s[t] = b1[t];
    __syncthreads();

    const int pl = t & 31;
    const int o0 = (t >> 5) << 3;

    unsigned long long a0 = *(const unsigned long long*)&b1s[o0 + 0];
    unsigned long long a1 = *(const unsigned long long*)&b1s[o0 + 2];
    unsigned long long a2 = *(const unsigned long long*)&b1s[o0 + 4];
    unsigned long long a3 = *(const unsigned long long*)&b1s[o0 + 6];

#pragma unroll 4
    for (int c = 0; c < 256; c++) {
        unsigned long long x2 = pack2(cur[c * 33 + pl]);
        ulonglong2 wa = *(const ulonglong2*)&wc[c * WSTR + o0];
        ulonglong2 wb = *(const ulonglong2*)&wc[c * WSTR + o0 + 4];
        a0 = fma2(x2, wa.x, a0);
        a1 = fma2(x2, wa.y, a1);
        a2 = fma2(x2, wb.x, a2);
        a3 = fma2(x2, wb.y, a3);
    }

    float2 r0 = unpack2(a0), r1 = unpack2(a1), r2 = unpack2(a2), r3 = unpack2(a3);
    float* dst = &g_bias[(b * P_ + p0 + pl) * BN_ + o0];
    *(float4*)(dst)     = make_float4(r0.x, r0.y, r1.x, r1.y);
    *(float4*)(dst + 4) = make_float4(r2.x, r2.y, r3.x, r3.y);
}

// ===================== kernel B: fused main =====================
// grid = B_ * (P_/PT) = 2048, block = 256 (8 warps), 1 CTA/SM
__global__ void __launch_bounds__(256, 1)
main_kernel(const float* __restrict__ nbr,
            const float* __restrict__ validity,
            const float* __restrict__ edge,
            const float* __restrict__ w1,
            const float* __restrict__ w2g,
            float* __restrict__ out) {
    extern __shared__ float sm[];
    float* xs    = sm;                        // [CAUG][XSTR]: 4 p-slices, m = pi*32+k
    float* W     = xs + CAUG * XSTR;          // [CAUG][WSTR]
    float* biass = W + CAUG * WSTR;           // [PT][64]
    float* parts = biass + PT * BN_;          // [8][PT][32]
    float* wts   = parts + 8 * PT * 32;       // [PT][32]
    float* vals  = wts + PT * 32;             // [PT][32]
    float* w2s   = vals + PT * 32;            // [64]

    const int t  = threadIdx.x;
    const int b  = blockIdx.x >> 8;           // 256 tiles per batch
    const int p0 = (blockIdx.x & 255) * PT;
    const int w  = t >> 5;
    const int k  = t & 31;
    const int o0 = w << 3;                    // 8 o's per warp

    const uint32_t xs_u = (uint32_t)__cvta_generic_to_shared(xs);

    // ---- issue async x-tile loads: row c -> 128 contiguous floats (4p x 32k) ----
    // group 0: rows [0, 130), group 1: rows [130, 260)
    {
        const float* nb = nbr  + ((size_t)(b * H_) * P_ + p0) * K_;
        const float* eb = edge + ((size_t)(b * E_) * P_ + p0) * K_;
        for (int idx = t; idx < HALF_ROWS * 32; idx += 256) {
            int c = idx >> 5, s = idx & 31;
            const float* src = nb + (size_t)c * (P_ * K_) + 4 * s;
            cp16(xs_u + (uint32_t)(c * XSTR + 4 * s) * 4u, src);
        }
        asm volatile("cp.async.commit_group;" ::: "memory");
        for (int idx = HALF_ROWS * 32 + t; idx < CAUG * 32; idx += 256) {
            int c = idx >> 5, s = idx & 31;
            const float* src = (c < 256) ? (nb + (size_t)c * (P_ * K_) + 4 * s)
                                         : (eb + (size_t)(c - 256) * (P_ * K_) + 4 * s);
            cp16(xs_u + (uint32_t)(c * XSTR + 4 * s) * 4u, src);
        }
        asm volatile("cp.async.commit_group;" ::: "memory");
    }

    // ---- regular loads (overlap with cp.async) ----
    for (int idx = t; idx < CAUG * 64; idx += 256) {
        int o = idx / CAUG, c = idx % CAUG;
        int col = (c < 256) ? (256 + c) : (512 + (c - 256));
        W[c * WSTR + o] = w1[o * W1COLS + col];
    }
    if (t < 64) w2s[t] = w2g[t];
    if (t < PT * 32) vals[t] = validity[(b * P_ + p0) * K_ + t];     // [pi][k] contiguous
    if (t < PT * 64) biass[t] = g_bias[(b * P_ + p0) * BN_ + t];     // [pi][o] contiguous

    // ---- accumulators: acc[o-pair j][pi] ----
    unsigned long long acc[4][PT];

    asm volatile("cp.async.wait_group 1;" ::: "memory");
    __syncthreads();   // half 1 of xs + W + biass + vals visible

#pragma unroll
    for (int j = 0; j < 4; j++)
#pragma unroll
        for (int pi = 0; pi < PT; pi++)
            acc[j][pi] = *(const unsigned long long*)&biass[pi * BN_ + o0 + 2 * j];

    // ---- GEMM half 1 ----
#pragma unroll 2
    for (int c = 0; c < HALF_ROWS; c++) {
        const float* wr = &W[c * WSTR + o0];
        ulonglong2 wa = *(const ulonglong2*)(wr);
        ulonglong2 wb = *(const ulonglong2*)(wr + 4);
        const float* xr = &xs[c * XSTR + k];
#pragma unroll
        for (int pi = 0; pi < PT; pi++) {
            unsigned long long x2 = pack2(xr[pi * 32]);
            acc[0][pi] = fma2(x2, wa.x, acc[0][pi]);
            acc[1][pi] = fma2(x2, wa.y, acc[1][pi]);
            acc[2][pi] = fma2(x2, wb.x, acc[2][pi]);
            acc[3][pi] = fma2(x2, wb.y, acc[3][pi]);
        }
    }

    asm volatile("cp.async.wait_group 0;" ::: "memory");
    __syncthreads();   // half 2 of xs visible

    // ---- GEMM half 2 ----
#pragma unroll 2
    for (int c = HALF_ROWS; c < CAUG; c++) {
        const float* wr = &W[c * WSTR + o0];
        ulonglong2 wa = *(const ulonglong2*)(wr);
        ulonglong2 wb = *(const ulonglong2*)(wr + 4);
        const float* xr = &xs[c * XSTR + k];
#pragma unroll
        for (int pi = 0; pi < PT; pi++) {
            unsigned long long x2 = pack2(xr[pi * 32]);
            acc[0][pi] = fma2(x2, wa.x, acc[0][pi]);
            acc[1][pi] = fma2(x2, wa.y, acc[1][pi]);
            acc[2][pi] = fma2(x2, wb.x, acc[2][pi]);
            acc[3][pi] = fma2(x2, wb.y, acc[3][pi]);
        }
    }

    // ---- relu + w2 partial dot ----
    {
        float w2r[8];
#pragma unroll
        for (int j = 0; j < 8; j++) w2r[j] = w2s[o0 + j];
#pragma unroll
        for (int pi = 0; pi < PT; pi++) {
            float2 h0 = unpack2(acc[0][pi]), h1 = unpack2(acc[1][pi]);
            float2 h2 = unpack2(acc[2][pi]), h3 = unpack2(acc[3][pi]);
            float part = fmaxf(h0.x, 0.f) * w2r[0] + fmaxf(h0.y, 0.f) * w2r[1]
                       + fmaxf(h1.x, 0.f) * w2r[2] + fmaxf(h1.y, 0.f) * w2r[3]
                       + fmaxf(h2.x, 0.f) * w2r[4] + fmaxf(h2.y, 0.f) * w2r[5]
                       + fmaxf(h3.x, 0.f) * w2r[6] + fmaxf(h3.y, 0.f) * w2r[7];
            parts[(w * PT + pi) * 32 + k] = part;
        }
    }
    __syncthreads();

    // ---- softmax: warp pi handles p0+pi ----
    const float NEG_INF = __int_as_float(0xff800000);
    if (w < PT) {
        const int pi = w;
        float lg = 0.f;
#pragma unroll
        for (int g = 0; g < 8; g++) lg += parts[(g * PT + pi) * 32 + k];
        bool valid = vals[pi * 32 + k] > 0.5f;
        float lv = valid ? lg : NEG_INF;
        float m = lv;
#pragma unroll
        for (int s = 16; s; s >>= 1) m = fmaxf(m, __shfl_xor_sync(0xffffffffu, m, s));
        bool any = (m > NEG_INF);
        float e = (valid && any) ? __expf(lg - m) : 0.f;
        float ssum = e;
#pragma unroll
        for (int s = 16; s; s >>= 1) ssum += __shfl_xor_sync(0xffffffffu, ssum, s);
        wts[pi * 32 + k] = any ? (e / ssum) : 0.f;
    }
    __syncthreads();

    // ---- pooled: warp reads whole c-row (128 floats, conflict-free), 8-lane reduce ----
    {
        const int pig = k >> 3;               // this lane's p-index
        const int k0  = (k & 7) * 4;          // this lane's k-range
        float4 wtv = *(const float4*)&wts[pig * 32 + k0];
        for (int c = w; c < 256; c += 8) {
            float4 v = *(const float4*)&xs[c * XSTR + 4 * k];
            float partial = v.x * wtv.x + v.y * wtv.y + v.z * wtv.z + v.w * wtv.w;
            partial += __shfl_down_sync(0xffffffffu, partial, 4);
            partial += __shfl_down_sync(0xffffffffu, partial, 2);
            partial += __shfl_down_sync(0xffffffffu, partial, 1);
            if ((k & 7) == 0)
                out[(b * H_ + c) * P_ + p0 + pig] = partial;
        }
    }
}

// ===================== launch =====================
extern "C" void kernel_launch(void* const* d_in, const int* in_sizes, int n_in,
                              void* d_out, int out_size) {
    const float* current  = (const float*)d_in[0];
    const float* nbr      = (const float*)d_in[1];
    const float* validity = (const float*)d_in[2];
    const float* edge     = (const float*)d_in[3];
    const float* w1       = (const float*)d_in[4];
    const float* b1       = (const float*)d_in[5];
    const float* w2       = (const float*)d_in[6];
    // d_in[7] = b2: shift-invariant under softmax, unused
    float* out = (float*)d_out;

    cudaFuncSetAttribute(bias_kernel, cudaFuncAttributeMaxDynamicSharedMemorySize, BIAS_SMEM_BYTES);
    cudaFuncSetAttribute(main_kernel, cudaFuncAttributeMaxDynamicSharedMemorySize, MAIN_SMEM_BYTES);

    bias_kernel<<<B_ * (P_ / 32), 256, BIAS_SMEM_BYTES>>>(current, w1, b1);
    main_kernel<<<B_ * (P_ / PT), 256, MAIN_SMEM_BYTES>>>(nbr, validity, edge, w1, w2, out);
}

// round 13
// speedup vs baseline: 1.0003x; 1.0003x over previous
#include <cuda_runtime.h>
#include <math.h>
#include <stdint.h>

#define B_ 8
#define H_ 256
#define P_ 1024
#define K_ 32
#define E_ 4
#define BN_ 64
#define W1COLS 516
#define CAUG 260          // 256 nbr + 4 edge rows (augmented contraction)
#define WSTR 68           // W row stride (floats), 272B: 16B-aligned rows
#define XSTR 132          // x row stride (floats), 528B: 16B-aligned rows
#define PT 4              // p's per CTA tile
#define HALF_ROWS 130

#define MAIN_SMEM_FLOATS (CAUG*XSTR + CAUG*WSTR + PT*BN_ + 8*PT*32 + PT*32 + PT*32 + 64)
#define MAIN_SMEM_BYTES  (MAIN_SMEM_FLOATS * 4)

#define BIAS_SMEM_FLOATS (256*WSTR + 256*33 + 64)
#define BIAS_SMEM_BYTES  (BIAS_SMEM_FLOATS * 4)

// scratch: bias[b][p][o] = b1[o] + sum_c current[b,c,p] * w1c[o,c]
__device__ float g_bias[B_ * P_ * BN_];

// ---- packed fp32x2 helpers ----
static __device__ __forceinline__ unsigned long long pack2(float x) {
    unsigned long long r;
    asm("mov.b64 %0, {%1, %1};" : "=l"(r) : "f"(x));
    return r;
}
static __device__ __forceinline__ unsigned long long fma2(unsigned long long a,
                                                          unsigned long long b,
                                                          unsigned long long c) {
    unsigned long long d;
    asm("fma.rn.f32x2 %0, %1, %2, %3;" : "=l"(d) : "l"(a), "l"(b), "l"(c));
    return d;
}
static __device__ __forceinline__ float2 unpack2(unsigned long long v) {
    float2 f;
    asm("mov.b64 {%0, %1}, %2;" : "=f"(f.x), "=f"(f.y) : "l"(v));
    return f;
}
static __device__ __forceinline__ void cp16(uint32_t dst, const void* src) {
    asm volatile("cp.async.cg.shared.global [%0], [%1], 16;" :: "r"(dst), "l"(src));
}

// ===================== kernel A: bias precompute =====================
__global__ void __launch_bounds__(256, 2)
bias_kernel(const float* __restrict__ current,
            const float* __restrict__ w1,
            const float* __restrict__ b1) {
    extern __shared__ float sm[];
    float* wc  = sm;                    // [256][WSTR]
    float* cur = wc + 256 * WSTR;       // [256][33]
    float* b1s = cur + 256 * 33;        // [64]

    const int b  = blockIdx.x >> 5;
    const int p0 = (blockIdx.x & 31) << 5;
    const int t  = threadIdx.x;

    for (int idx = t; idx < 256 * 64; idx += 256) {
        int o = idx >> 8, c = idx & 255;
        wc[c * WSTR + o] = w1[o * W1COLS + c];
    }
    for (int idx = t; idx < 256 * 32; idx += 256) {
        int c = idx >> 5, pl = idx & 31;
        cur[c * 33 + pl] = current[(b * H_ + c) * P_ + p0 + pl];
    }
    if (t < 64) b1s[t] = b1[t];
    __syncthreads();

    const int pl = t & 31;
    const int o0 = (t >> 5) << 3;

    unsigned long long a0 = *(const unsigned long long*)&b1s[o0 + 0];
    unsigned long long a1 = *(const unsigned long long*)&b1s[o0 + 2];
    unsigned long long a2 = *(const unsigned long long*)&b1s[o0 + 4];
    unsigned long long a3 = *(const unsigned long long*)&b1s[o0 + 6];

#pragma unroll 4
    for (int c = 0; c < 256; c++) {
        unsigned long long x2 = pack2(cur[c * 33 + pl]);
        ulonglong2 wa = *(const ulonglong2*)&wc[c * WSTR + o0];
        ulonglong2 wb = *(const ulonglong2*)&wc[c * WSTR + o0 + 4];
        a0 = fma2(x2, wa.x, a0);
        a1 = fma2(x2, wa.y, a1);
        a2 = fma2(x2, wb.x, a2);
        a3 = fma2(x2, wb.y, a3);
    }

    float2 r0 = unpack2(a0), r1 = unpack2(a1), r2 = unpack2(a2), r3 = unpack2(a3);
    float* dst = &g_bias[(b * P_ + p0 + pl) * BN_ + o0];
    *(float4*)(dst)     = make_float4(r0.x, r0.y, r1.x, r1.y);
    *(float4*)(dst + 4) = make_float4(r2.x, r2.y, r3.x, r3.y);
}

// ===================== kernel B: fused main =====================
// grid = B_ * (P_/PT) = 2048, block = 256 (8 warps), 1 CTA/SM
__global__ void __launch_bounds__(256, 1)
main_kernel(const float* __restrict__ nbr,
            const float* __restrict__ validity,
            const float* __restrict__ edge,
            const float* __restrict__ w1,
            const float* __restrict__ w2g,
            float* __restrict__ out) {
    extern __shared__ float sm[];
    float* xs    = sm;                        // [CAUG][XSTR]: 4 p-slices, m = pi*32+k
    float* W     = xs + CAUG * XSTR;          // [CAUG][WSTR]
    float* biass = W + CAUG * WSTR;           // [PT][64]
    float* parts = biass + PT * BN_;          // [8][PT][32]
    float* wts   = parts + 8 * PT * 32;       // [PT][32]
    float* vals  = wts + PT * 32;             // [PT][32]
    float* w2s   = vals + PT * 32;            // [64]

    const int t  = threadIdx.x;
    const int b  = blockIdx.x >> 8;           // 256 tiles per batch
    const int p0 = (blockIdx.x & 255) * PT;
    const int w  = t >> 5;
    const int k  = t & 31;
    const int o0 = w << 3;                    // 8 o's per warp

    const uint32_t xs_u = (uint32_t)__cvta_generic_to_shared(xs);

    // ---- issue async x-tile loads: row c -> 128 contiguous floats (4p x 32k) ----
    // group 0: rows [0, 130), group 1: rows [130, 260)
    {
        const float* nb = nbr  + ((size_t)(b * H_) * P_ + p0) * K_;
        const float* eb = edge + ((size_t)(b * E_) * P_ + p0) * K_;
        for (int idx = t; idx < HALF_ROWS * 32; idx += 256) {
            int c = idx >> 5, s = idx & 31;
            const float* src = nb + (size_t)c * (P_ * K_) + 4 * s;
            cp16(xs_u + (uint32_t)(c * XSTR + 4 * s) * 4u, src);
        }
        asm volatile("cp.async.commit_group;" ::: "memory");
        for (int idx = HALF_ROWS * 32 + t; idx < CAUG * 32; idx += 256) {
            int c = idx >> 5, s = idx & 31;
            const float* src = (c < 256) ? (nb + (size_t)c * (P_ * K_) + 4 * s)
                                         : (eb + (size_t)(c - 256) * (P_ * K_) + 4 * s);
            cp16(xs_u + (uint32_t)(c * XSTR + 4 * s) * 4u, src);
        }
        asm volatile("cp.async.commit_group;" ::: "memory");
    }

    // ---- regular loads (overlap with cp.async) ----
    for (int idx = t; idx < CAUG * 64; idx += 256) {
        int o = idx / CAUG, c = idx % CAUG;
        int col = (c < 256) ? (256 + c) : (512 + (c - 256));
        W[c * WSTR + o] = w1[o * W1COLS + col];
    }
    if (t < 64) w2s[t] = w2g[t];
    if (t < PT * 32) vals[t] = validity[(b * P_ + p0) * K_ + t];     // [pi][k] contiguous
    if (t < PT * 64) biass[t] = g_bias[(b * P_ + p0) * BN_ + t];     // [pi][o] contiguous

    // ---- accumulators: acc[o-pair j][pi] ----
    unsigned long long acc[4][PT];

    asm volatile("cp.async.wait_group 1;" ::: "memory");
    __syncthreads();   // half 1 of xs + W + biass + vals visible

#pragma unroll
    for (int j = 0; j < 4; j++)
#pragma unroll
        for (int pi = 0; pi < PT; pi++)
            acc[j][pi] = *(const unsigned long long*)&biass[pi * BN_ + o0 + 2 * j];

    // ---- GEMM half 1 ----
#pragma unroll 2
    for (int c = 0; c < HALF_ROWS; c++) {
        const float* wr = &W[c * WSTR + o0];
        ulonglong2 wa = *(const ulonglong2*)(wr);
        ulonglong2 wb = *(const ulonglong2*)(wr + 4);
        const float* xr = &xs[c * XSTR + k];
#pragma unroll
        for (int pi = 0; pi < PT; pi++) {
            unsigned long long x2 = pack2(xr[pi * 32]);
            acc[0][pi] = fma2(x2, wa.x, acc[0][pi]);
            acc[1][pi] = fma2(x2, wa.y, acc[1][pi]);
            acc[2][pi] = fma2(x2, wb.x, acc[2][pi]);
            acc[3][pi] = fma2(x2, wb.y, acc[3][pi]);
        }
    }

    asm volatile("cp.async.wait_group 0;" ::: "memory");
    __syncthreads();   // half 2 of xs visible

    // ---- GEMM half 2 ----
#pragma unroll 2
    for (int c = HALF_ROWS; c < CAUG; c++) {
        const float* wr = &W[c * WSTR + o0];
        ulonglong2 wa = *(const ulonglong2*)(wr);
        ulonglong2 wb = *(const ulonglong2*)(wr + 4);
        const float* xr = &xs[c * XSTR + k];
#pragma unroll
        for (int pi = 0; pi < PT; pi++) {
            unsigned long long x2 = pack2(xr[pi * 32]);
            acc[0][pi] = fma2(x2, wa.x, acc[0][pi]);
            acc[1][pi] = fma2(x2, wa.y, acc[1][pi]);
            acc[2][pi] = fma2(x2, wb.x, acc[2][pi]);
            acc[3][pi] = fma2(x2, wb.y, acc[3][pi]);
        }
    }

    // ---- relu + w2 partial dot ----
    {
        float w2r[8];
#pragma unroll
        for (int j = 0; j < 8; j++) w2r[j] = w2s[o0 + j];
#pragma unroll
        for (int pi = 0; pi < PT; pi++) {
            float2 h0 = unpack2(acc[0][pi]), h1 = unpack2(acc[1][pi]);
            float2 h2 = unpack2(acc[2][pi]), h3 = unpack2(acc[3][pi]);
            float part = fmaxf(h0.x, 0.f) * w2r[0] + fmaxf(h0.y, 0.f) * w2r[1]
                       + fmaxf(h1.x, 0.f) * w2r[2] + fmaxf(h1.y, 0.f) * w2r[3]
                       + fmaxf(h2.x, 0.f) * w2r[4] + fmaxf(h2.y, 0.f) * w2r[5]
                       + fmaxf(h3.x, 0.f) * w2r[6] + fmaxf(h3.y, 0.f) * w2r[7];
            parts[(w * PT + pi) * 32 + k] = part;
        }
    }
    __syncthreads();

    // ---- softmax: warp pi handles p0+pi ----
    const float NEG_INF = __int_as_float(0xff800000);
    if (w < PT) {
        const int pi = w;
        float lg = 0.f;
#pragma unroll
        for (int g = 0; g < 8; g++) lg += parts[(g * PT + pi) * 32 + k];
        bool valid = vals[pi * 32 + k] > 0.5f;
        float lv = valid ? lg : NEG_INF;
        float m = lv;
#pragma unroll
        for (int s = 16; s; s >>= 1) m = fmaxf(m, __shfl_xor_sync(0xffffffffu, m, s));
        bool any = (m > NEG_INF);
        float e = (valid && any) ? __expf(lg - m) : 0.f;
        float ssum = e;
#pragma unroll
        for (int s = 16; s; s >>= 1) ssum += __shfl_xor_sync(0xffffffffu, ssum, s);
        wts[pi * 32 + k] = any ? (e / ssum) : 0.f;
    }
    __syncthreads();

    // ---- pooled: warp reads whole c-row (128 floats, conflict-free), 8-lane reduce ----
    {
        const int pig = k >> 3;               // this lane's p-index
        const int k0  = (k & 7) * 4;          // this lane's k-range
        float4 wtv = *(const float4*)&wts[pig * 32 + k0];
        for (int c = w; c < 256; c += 8) {
            float4 v = *(const float4*)&xs[c * XSTR + 4 * k];
            float partial = v.x * wtv.x + v.y * wtv.y + v.z * wtv.z + v.w * wtv.w;
            partial += __shfl_down_sync(0xffffffffu, partial, 4);
            partial += __shfl_down_sync(0xffffffffu, partial, 2);
            partial += __shfl_down_sync(0xffffffffu, partial, 1);
            if ((k & 7) == 0)
                out[(b * H_ + c) * P_ + p0 + pig] = partial;
        }
    }
}

// ===================== launch =====================
extern "C" void kernel_launch(void* const* d_in, const int* in_sizes, int n_in,
                              void* d_out, int out_size) {
    const float* current  = (const float*)d_in[0];
    const float* nbr      = (const float*)d_in[1];
    const float* validity = (const float*)d_in[2];
    const float* edge     = (const float*)d_in[3];
    const float* w1       = (const float*)d_in[4];
    const float* b1       = (const float*)d_in[5];
    const float* w2       = (const float*)d_in[6];
    // d_in[7] = b2: shift-invariant under softmax, unused
    float* out = (float*)d_out;

    cudaFuncSetAttribute(bias_kernel, cudaFuncAttributeMaxDynamicSharedMemorySize, BIAS_SMEM_BYTES);
    cudaFuncSetAttribute(main_kernel, cudaFuncAttributeMaxDynamicSharedMemorySize, MAIN_SMEM_BYTES);

    bias_kernel<<<B_ * (P_ / 32), 256, BIAS_SMEM_BYTES>>>(current, w1, b1);
    main_kernel<<<B_ * (P_ / PT), 256, MAIN_SMEM_BYTES>>>(nbr, validity, edge, w1, w2, out);
}

// round 14
// speedup vs baseline: 1.0051x; 1.0048x over previous
#include <cuda_runtime.h>
#include <math.h>
#include <stdint.h>

#define B_ 8
#define H_ 256
#define P_ 1024
#define K_ 32
#define E_ 4
#define BN_ 64
#define W1COLS 516
#define CAUG 260          // 256 nbr + 4 edge rows (augmented contraction)
#define WSTR 68           // W row stride (floats), 272B: 16B-aligned rows
#define XSTR 132          // x row stride (floats), 528B: 16B-aligned rows
#define PT 4              // p's per CTA tile
#define HALF_ROWS 130

#define MAIN_SMEM_FLOATS (CAUG*XSTR + CAUG*WSTR + PT*BN_ + 8*PT*32 + PT*32 + PT*32 + 64)
#define MAIN_SMEM_BYTES  (MAIN_SMEM_FLOATS * 4)

#define BIAS_SMEM_FLOATS (256*WSTR + 256*33 + 64)
#define BIAS_SMEM_BYTES  (BIAS_SMEM_FLOATS * 4)

// scratch: bias[b][p][o] = b1[o] + sum_c current[b,c,p] * w1c[o,c]
__device__ float g_bias[B_ * P_ * BN_];

// ---- packed fp32x2 helpers ----
static __device__ __forceinline__ unsigned long long pack2(float x) {
    unsigned long long r;
    asm("mov.b64 %0, {%1, %1};" : "=l"(r) : "f"(x));
    return r;
}
static __device__ __forceinline__ unsigned long long fma2(unsigned long long a,
                                                          unsigned long long b,
                                                          unsigned long long c) {
    unsigned long long d;
    asm("fma.rn.f32x2 %0, %1, %2, %3;" : "=l"(d) : "l"(a), "l"(b), "l"(c));
    return d;
}
static __device__ __forceinline__ float2 unpack2(unsigned long long v) {
    float2 f;
    asm("mov.b64 {%0, %1}, %2;" : "=f"(f.x), "=f"(f.y) : "l"(v));
    return f;
}
static __device__ __forceinline__ void cp16(uint32_t dst, const void* src) {
    asm volatile("cp.async.cg.shared.global [%0], [%1], 16;" :: "r"(dst), "l"(src));
}

// ===================== kernel A: bias precompute =====================
__global__ void __launch_bounds__(256, 2)
bias_kernel(const float* __restrict__ current,
            const float* __restrict__ w1,
            const float* __restrict__ b1) {
    extern __shared__ float sm[];
    float* wc  = sm;                    // [256][WSTR]
    float* cur = wc + 256 * WSTR;       // [256][33]
    float* b1s = cur + 256 * 33;        // [64]

    const int b  = blockIdx.x >> 5;
    const int p0 = (blockIdx.x & 31) << 5;
    const int t  = threadIdx.x;

    for (int idx = t; idx < 256 * 64; idx += 256) {
        int o = idx >> 8, c = idx & 255;
        wc[c * WSTR + o] = w1[o * W1COLS + c];
    }
    for (int idx = t; idx < 256 * 32; idx += 256) {
        int c = idx >> 5, pl = idx & 31;
        cur[c * 33 + pl] = current[(b * H_ + c) * P_ + p0 + pl];
    }
    if (t < 64) b1s[t] = b1[t];
    __syncthreads();

    const int pl = t & 31;
    const int o0 = (t >> 5) << 3;

    unsigned long long a0 = *(const unsigned long long*)&b1s[o0 + 0];
    unsigned long long a1 = *(const unsigned long long*)&b1s[o0 + 2];
    unsigned long long a2 = *(const unsigned long long*)&b1s[o0 + 4];
    unsigned long long a3 = *(const unsigned long long*)&b1s[o0 + 6];

#pragma unroll 4
    for (int c = 0; c < 256; c++) {
        unsigned long long x2 = pack2(cur[c * 33 + pl]);
        ulonglong2 wa = *(const ulonglong2*)&wc[c * WSTR + o0];
        ulonglong2 wb = *(const ulonglong2*)&wc[c * WSTR + o0 + 4];
        a0 = fma2(x2, wa.x, a0);
        a1 = fma2(x2, wa.y, a1);
        a2 = fma2(x2, wb.x, a2);
        a3 = fma2(x2, wb.y, a3);
    }

    float2 r0 = unpack2(a0), r1 = unpack2(a1), r2 = unpack2(a2), r3 = unpack2(a3);
    float* dst = &g_bias[(b * P_ + p0 + pl) * BN_ + o0];
    *(float4*)(dst)     = make_float4(r0.x, r0.y, r1.x, r1.y);
    *(float4*)(dst + 4) = make_float4(r2.x, r2.y, r3.x, r3.y);
}

// ===================== kernel B: fused main =====================
// grid = B_ * (P_/PT) = 2048, block = 256 (8 warps), 1 CTA/SM
__global__ void __launch_bounds__(256, 1)
main_kernel(const float* __restrict__ nbr,
            const float* __restrict__ validity,
            const float* __restrict__ edge,
            const float* __restrict__ w1,
            const float* __restrict__ w2g,
            float* __restrict__ out) {
    extern __shared__ float sm[];
    float* xs    = sm;                        // [CAUG][XSTR]: 4 p-slices, m = pi*32+k
    float* W     = xs + CAUG * XSTR;          // [CAUG][WSTR]
    float* biass = W + CAUG * WSTR;           // [PT][64]
    float* parts = biass + PT * BN_;          // [8][PT][32]
    float* wts   = parts + 8 * PT * 32;       // [PT][32]
    float* vals  = wts + PT * 32;             // [PT][32]
    float* w2s   = vals + PT * 32;            // [64]

    const int t  = threadIdx.x;
    const int b  = blockIdx.x >> 8;           // 256 tiles per batch
    const int p0 = (blockIdx.x & 255) * PT;
    const int w  = t >> 5;
    const int k  = t & 31;
    const int o0 = w << 3;                    // 8 o's per warp

    const uint32_t xs_u = (uint32_t)__cvta_generic_to_shared(xs);

    // ---- issue async x-tile loads: row c -> 128 contiguous floats (4p x 32k) ----
    // group 0: rows [0, 130), group 1: rows [130, 260)
    {
        const float* nb = nbr  + ((size_t)(b * H_) * P_ + p0) * K_;
        const float* eb = edge + ((size_t)(b * E_) * P_ + p0) * K_;
        for (int idx = t; idx < HALF_ROWS * 32; idx += 256) {
            int c = idx >> 5, s = idx & 31;
            const float* src = nb + (size_t)c * (P_ * K_) + 4 * s;
            cp16(xs_u + (uint32_t)(c * XSTR + 4 * s) * 4u, src);
        }
        asm volatile("cp.async.commit_group;" ::: "memory");
        for (int idx = HALF_ROWS * 32 + t; idx < CAUG * 32; idx += 256) {
            int c = idx >> 5, s = idx & 31;
            const float* src = (c < 256) ? (nb + (size_t)c * (P_ * K_) + 4 * s)
                                         : (eb + (size_t)(c - 256) * (P_ * K_) + 4 * s);
            cp16(xs_u + (uint32_t)(c * XSTR + 4 * s) * 4u, src);
        }
        asm volatile("cp.async.commit_group;" ::: "memory");
    }

    // ---- regular loads (overlap with cp.async) ----
    for (int idx = t; idx < CAUG * 64; idx += 256) {
        int o = idx / CAUG, c = idx % CAUG;
        int col = (c < 256) ? (256 + c) : (512 + (c - 256));
        W[c * WSTR + o] = w1[o * W1COLS + col];
    }
    if (t < 64) w2s[t] = w2g[t];
    if (t < PT * 32) vals[t] = validity[(b * P_ + p0) * K_ + t];     // [pi][k] contiguous
    if (t < PT * 64) biass[t] = g_bias[(b * P_ + p0) * BN_ + t];     // [pi][o] contiguous

    // ---- accumulators: acc[o-pair j][pi] ----
    unsigned long long acc[4][PT];

    asm volatile("cp.async.wait_group 1;" ::: "memory");
    __syncthreads();   // half 1 of xs + W + biass + vals visible

#pragma unroll
    for (int j = 0; j < 4; j++)
#pragma unroll
        for (int pi = 0; pi < PT; pi++)
            acc[j][pi] = *(const unsigned long long*)&biass[pi * BN_ + o0 + 2 * j];

    // ---- GEMM half 1 ----
#pragma unroll 2
    for (int c = 0; c < HALF_ROWS; c++) {
        const float* wr = &W[c * WSTR + o0];
        ulonglong2 wa = *(const ulonglong2*)(wr);
        ulonglong2 wb = *(const ulonglong2*)(wr + 4);
        const float* xr = &xs[c * XSTR + k];
#pragma unroll
        for (int pi = 0; pi < PT; pi++) {
            unsigned long long x2 = pack2(xr[pi * 32]);
            acc[0][pi] = fma2(x2, wa.x, acc[0][pi]);
            acc[1][pi] = fma2(x2, wa.y, acc[1][pi]);
            acc[2][pi] = fma2(x2, wb.x, acc[2][pi]);
            acc[3][pi] = fma2(x2, wb.y, acc[3][pi]);
        }
    }

    asm volatile("cp.async.wait_group 0;" ::: "memory");
    __syncthreads();   // half 2 of xs visible

    // ---- GEMM half 2 ----
#pragma unroll 2
    for (int c = HALF_ROWS; c < CAUG; c++) {
        const float* wr = &W[c * WSTR + o0];
        ulonglong2 wa = *(const ulonglong2*)(wr);
        ulonglong2 wb = *(const ulonglong2*)(wr + 4);
        const float* xr = &xs[c * XSTR + k];
#pragma unroll
        for (int pi = 0; pi < PT; pi++) {
            unsigned long long x2 = pack2(xr[pi * 32]);
            acc[0][pi] = fma2(x2, wa.x, acc[0][pi]);
            acc[1][pi] = fma2(x2, wa.y, acc[1][pi]);
            acc[2][pi] = fma2(x2, wb.x, acc[2][pi]);
            acc[3][pi] = fma2(x2, wb.y, acc[3][pi]);
        }
    }

    // ---- relu + w2 partial dot ----
    {
        float w2r[8];
#pragma unroll
        for (int j = 0; j < 8; j++) w2r[j] = w2s[o0 + j];
#pragma unroll
        for (int pi = 0; pi < PT; pi++) {
            float2 h0 = unpack2(acc[0][pi]), h1 = unpack2(acc[1][pi]);
            float2 h2 = unpack2(acc[2][pi]), h3 = unpack2(acc[3][pi]);
            float part = fmaxf(h0.x, 0.f) * w2r[0] + fmaxf(h0.y, 0.f) * w2r[1]
                       + fmaxf(h1.x, 0.f) * w2r[2] + fmaxf(h1.y, 0.f) * w2r[3]
                       + fmaxf(h2.x, 0.f) * w2r[4] + fmaxf(h2.y, 0.f) * w2r[5]
                       + fmaxf(h3.x, 0.f) * w2r[6] + fmaxf(h3.y, 0.f) * w2r[7];
            parts[(w * PT + pi) * 32 + k] = part;
        }
    }
    __syncthreads();

    // ---- softmax: warp pi handles p0+pi ----
    const float NEG_INF = __int_as_float(0xff800000);
    if (w < PT) {
        const int pi = w;
        float lg = 0.f;
#pragma unroll
        for (int g = 0; g < 8; g++) lg += parts[(g * PT + pi) * 32 + k];
        bool valid = vals[pi * 32 + k] > 0.5f;
        float lv = valid ? lg : NEG_INF;
        float m = lv;
#pragma unroll
        for (int s = 16; s; s >>= 1) m = fmaxf(m, __shfl_xor_sync(0xffffffffu, m, s));
        bool any = (m > NEG_INF);
        float e = (valid && any) ? __expf(lg - m) : 0.f;
        float ssum = e;
#pragma unroll
        for (int s = 16; s; s >>= 1) ssum += __shfl_xor_sync(0xffffffffu, ssum, s);
        wts[pi * 32 + k] = any ? (e / ssum) : 0.f;
    }
    __syncthreads();

    // ---- pooled: warp reads whole c-row (128 floats, conflict-free), 8-lane reduce ----
    {
        const int pig = k >> 3;               // this lane's p-index
        const int k0  = (k & 7) * 4;          // this lane's k-range
        float4 wtv = *(const float4*)&wts[pig * 32 + k0];
        for (int c = w; c < 256; c += 8) {
            float4 v = *(const float4*)&xs[c * XSTR + 4 * k];
            float partial = v.x * wtv.x + v.y * wtv.y + v.z * wtv.z + v.w * wtv.w;
            partial += __shfl_down_sync(0xffffffffu, partial, 4);
            partial += __shfl_down_sync(0xffffffffu, partial, 2);
            partial += __shfl_down_sync(0xffffffffu, partial, 1);
            if ((k & 7) == 0)
                out[(b * H_ + c) * P_ + p0 + pig] = partial;
        }
    }
}

// ===================== launch =====================
extern "C" void kernel_launch(void* const* d_in, const int* in_sizes, int n_in,
                              void* d_out, int out_size) {
    const float* current  = (const float*)d_in[0];
    const float* nbr      = (const float*)d_in[1];
    const float* validity = (const float*)d_in[2];
    const float* edge     = (const float*)d_in[3];
    const float* w1       = (const float*)d_in[4];
    const float* b1       = (const float*)d_in[5];
    const float* w2       = (const float*)d_in[6];
    // d_in[7] = b2: shift-invariant under softmax, unused
    float* out = (float*)d_out;

    cudaFuncSetAttribute(bias_kernel, cudaFuncAttributeMaxDynamicSharedMemorySize, BIAS_SMEM_BYTES);
    cudaFuncSetAttribute(main_kernel, cudaFuncAttributeMaxDynamicSharedMemorySize, MAIN_SMEM_BYTES);

    bias_kernel<<<B_ * (P_ / 32), 256, BIAS_SMEM_BYTES>>>(current, w1, b1);
    main_kernel<<<B_ * (P_ / PT), 256, MAIN_SMEM_BYTES>>>(nbr, validity, edge, w1, w2, out);
}